// round 2
// baseline (speedup 1.0000x reference)
#include <cuda_runtime.h>
#include <cstddef>

#define TLEN 512
#define NC 15
#define PADL 15
#define NSEQ 4096
#define NWARPS 512

// per-warp partial sums of nll (8 sequences each)
__device__ float g_partials[NWARPS];

// Broadcast a_i (owned by sub-lane i>>2, register i&3) within each 4-lane group,
// accumulate into split accumulators (even i -> *a, odd i -> *b) to shorten FMA chains.
#define STEP_I(i, AV) do { \
    float r = __shfl_sync(0xffffffffu, (AV), (i) >> 2, 4); \
    if ((i) & 1) { \
        s0b = fmaf(r, eT[(i)][0], s0b); s1b = fmaf(r, eT[(i)][1], s1b); \
        s2b = fmaf(r, eT[(i)][2], s2b); s3b = fmaf(r, eT[(i)][3], s3b); \
    } else { \
        s0a = fmaf(r, eT[(i)][0], s0a); s1a = fmaf(r, eT[(i)][1], s1a); \
        s2a = fmaf(r, eT[(i)][2], s2a); s3a = fmaf(r, eT[(i)][3], s3a); \
    } \
} while (0)

__global__ __launch_bounds__(64, 1)
void crf_fwd(const float* __restrict__ logits, const int* __restrict__ yt,
             const float* __restrict__ trans) {
    __shared__ float sT[256];   // raw transitions (padded with zeros to 256)
    int tid = threadIdx.x;
    for (int i = tid; i < 256; i += 64) sT[i] = (i < 225) ? trans[i] : 0.0f;
    __syncthreads();

    int lane = tid & 31;
    int g = lane >> 2;          // group (sequence within warp), 0..7
    int c = lane & 3;           // sub-lane: owns tags j = 4c..4c+3
    int warpId = blockIdx.x * 2 + (tid >> 5);
    int b = warpId * 8 + g;     // sequence index, always < 4096

    // exp(transitions) columns owned by this lane; column j=15 (pad slot) = 0
    float eT[15][4];
#pragma unroll
    for (int i = 0; i < 15; i++) {
#pragma unroll
        for (int k = 0; k < 4; k++) {
            int j = 4 * c + k;
            eT[i][k] = (j < 15) ? __expf(sT[i * 15 + j]) : 0.0f;
        }
    }

    const float* lg = logits + (size_t)b * (TLEN * NC);
    const int*   yb = yt + (size_t)b * TLEN;
    int j0 = 4 * c;
    int j3 = (c == 3) ? 14 : j0 + 3;   // clamp OOB tag-15 load (value never used)

    // ---- t = 0 ----
    float em0 = lg[j0], em1 = lg[j0 + 1], em2 = lg[j0 + 2], em3 = lg[j3];
    int ycur = yb[0];
    bool mask = (ycur != PADL);
    float a0 = __expf(em0), a1 = __expf(em1), a2 = __expf(em2);
    float a3 = (c == 3) ? 0.0f : __expf(em3);   // pad tag slot stays exactly 0
    int E = 0;                                   // exact power-of-2 renorm exponent
    float em_acc = 0.0f, tr_acc = 0.0f;
    em_acc += (mask && ycur == j0    ) ? em0 : 0.0f;
    em_acc += (mask && ycur == j0 + 1) ? em1 : 0.0f;
    em_acc += (mask && ycur == j0 + 2) ? em2 : 0.0f;
    em_acc += (mask && ycur == j0 + 3) ? em3 : 0.0f;

    // prefetch t=1
    const float* p1 = lg + NC;
    float n0 = p1[j0], n1 = p1[j0 + 1], n2 = p1[j0 + 2], n3 = p1[j3];
    int ynext = yb[1];

    int yprev; bool pmask;

    for (int t = 1; t < TLEN; t++) {
        em0 = n0; em1 = n1; em2 = n2; em3 = n3;
        yprev = ycur; pmask = mask;
        ycur = ynext;

        // prefetch t+1 (clamped; duplicate last row is harmless)
        int tn = (t + 1 < TLEN) ? (t + 1) : (TLEN - 1);
        const float* pn = lg + (size_t)tn * NC;
        n0 = pn[j0]; n1 = pn[j0 + 1]; n2 = pn[j0 + 2]; n3 = pn[j3];
        ynext = yb[tn];

        mask = (ycur != PADL);

        // s_k = sum_i a_i * expT[i][4c+k]   (linear-space forward matvec)
        float s0a = 0, s0b = 0, s1a = 0, s1b = 0;
        float s2a = 0, s2b = 0, s3a = 0, s3b = 0;
        STEP_I(0,  a0); STEP_I(1,  a1); STEP_I(2,  a2); STEP_I(3,  a3);
        STEP_I(4,  a0); STEP_I(5,  a1); STEP_I(6,  a2); STEP_I(7,  a3);
        STEP_I(8,  a0); STEP_I(9,  a1); STEP_I(10, a2); STEP_I(11, a3);
        STEP_I(12, a0); STEP_I(13, a1); STEP_I(14, a2);

        float w0 = __expf(em0) * (s0a + s0b);
        float w1 = __expf(em1) * (s1a + s1b);
        float w2 = __expf(em2) * (s2a + s2b);
        float w3 = __expf(em3) * (s3a + s3b);   // c==3: s3==0 -> stays 0

        // masked update (branch-free selects; masked step keeps old alpha)
        a0 = mask ? w0 : a0;
        a1 = mask ? w1 : a1;
        a2 = mask ? w2 : a2;
        a3 = mask ? w3 : a3;

        // gold-path emission pick (only owning lane matches; pad excluded by mask)
        em_acc += (mask && ycur == j0    ) ? em0 : 0.0f;
        em_acc += (mask && ycur == j0 + 1) ? em1 : 0.0f;
        em_acc += (mask && ycur == j0 + 2) ? em2 : 0.0f;
        em_acc += (mask && ycur == j0 + 3) ? em3 : 0.0f;
        // gold-path transition (one lane per group accumulates)
        float tv = sT[yprev * 15 + ycur];       // index <= 240 < 256, padded zeros
        tr_acc += (mask && pmask && c == 0) ? tv : 0.0f;

        // exact power-of-two renormalization every 8 steps (branch is warp-uniform)
        if ((t & 7) == 0) {
            float m = fmaxf(fmaxf(a0, a1), fmaxf(a2, a3));
            m = fmaxf(m, __shfl_xor_sync(0xffffffffu, m, 1, 4));
            m = fmaxf(m, __shfl_xor_sync(0xffffffffu, m, 2, 4));
            int ex = ((__float_as_int(m) >> 23) & 0xff) - 127;
            float sc = __int_as_float((127 - ex) << 23);   // exact 2^-ex
            a0 *= sc; a1 *= sc; a2 *= sc; a3 *= sc;
            E += ex;
        }
    }

    // logZ = E*ln2 + log(sum_j a_j)
    float sA = (a0 + a1) + (a2 + a3);
    sA += __shfl_xor_sync(0xffffffffu, sA, 1, 4);
    sA += __shfl_xor_sync(0xffffffffu, sA, 2, 4);
    float path = em_acc + tr_acc;
    path += __shfl_xor_sync(0xffffffffu, path, 1, 4);
    path += __shfl_xor_sync(0xffffffffu, path, 2, 4);

    float logZ = (float)E * 0.6931471805599453f + logf(sA);
    float nll = logZ - path;
    nll = fminf(fmaxf(nll, 0.0f), 1000000.0f);

    // nll is identical across the 4 lanes of a group; xor-4/8/16 sums one copy
    // per group (lanes mixed by these xors share lane&3), so lane 0 holds the
    // exact 8-sequence sum — NO dedup factor.
    float w = nll;
    w += __shfl_xor_sync(0xffffffffu, w, 4);
    w += __shfl_xor_sync(0xffffffffu, w, 8);
    w += __shfl_xor_sync(0xffffffffu, w, 16);
    if (lane == 0) g_partials[warpId] = w;
}

__global__ void crf_reduce(float* out) {
    __shared__ double s[NWARPS];
    int t = threadIdx.x;
    s[t] = (double)g_partials[t];
    __syncthreads();
    for (int o = NWARPS / 2; o > 0; o >>= 1) {
        if (t < o) s[t] += s[t + o];
        __syncthreads();
    }
    if (t == 0) out[0] = (float)(s[0] / (double)NSEQ);
}

extern "C" void kernel_launch(void* const* d_in, const int* in_sizes, int n_in,
                              void* d_out, int out_size) {
    const float* logits = (const float*)d_in[0];
    const int*   yt     = (const int*)d_in[1];
    const float* trans  = (const float*)d_in[2];
    crf_fwd<<<256, 64>>>(logits, yt, trans);
    crf_reduce<<<1, NWARPS>>>((float*)d_out);
}

// round 3
// speedup vs baseline: 1.0161x; 1.0161x over previous
#include <cuda_runtime.h>
#include <cstddef>

#define TLEN 512
#define NC 15
#define PADL 15
#define NSEQ 4096
#define NWARPS 512

// per-warp partial sums of nll (8 sequences each)
__device__ float g_partials[NWARPS];

// Broadcast a_i (owned by sub-lane i>>2, register i&3) within each 4-lane group,
// accumulate into split accumulators (even i -> *a, odd i -> *b) to shorten FMA chains.
#define STEP_I(i, AV) do { \
    float r = __shfl_sync(0xffffffffu, (AV), (i) >> 2, 4); \
    if ((i) & 1) { \
        s0b = fmaf(r, eT[(i)][0], s0b); s1b = fmaf(r, eT[(i)][1], s1b); \
        s2b = fmaf(r, eT[(i)][2], s2b); s3b = fmaf(r, eT[(i)][3], s3b); \
    } else { \
        s0a = fmaf(r, eT[(i)][0], s0a); s1a = fmaf(r, eT[(i)][1], s1a); \
        s2a = fmaf(r, eT[(i)][2], s2a); s3a = fmaf(r, eT[(i)][3], s3a); \
    } \
} while (0)

__global__ __launch_bounds__(64, 1)
void crf_fwd(const float* __restrict__ logits, const int* __restrict__ yt,
             const float* __restrict__ trans) {
    __shared__ float sT[256];   // raw transitions (padded with zeros to 256)
    int tid = threadIdx.x;
    for (int i = tid; i < 256; i += 64) sT[i] = (i < 225) ? trans[i] : 0.0f;
    __syncthreads();

    int lane = tid & 31;
    int g = lane >> 2;          // group (sequence within warp), 0..7
    int c = lane & 3;           // sub-lane: owns tags j = 4c..4c+3
    int warpId = blockIdx.x * 2 + (tid >> 5);
    int b = warpId * 8 + g;     // sequence index, always < 4096

    // exp(transitions) columns owned by this lane; column j=15 (pad slot) = 0
    float eT[15][4];
#pragma unroll
    for (int i = 0; i < 15; i++) {
#pragma unroll
        for (int k = 0; k < 4; k++) {
            int j = 4 * c + k;
            eT[i][k] = (j < 15) ? __expf(sT[i * 15 + j]) : 0.0f;
        }
    }

    const float* lg = logits + (size_t)b * (TLEN * NC);
    const int*   yb = yt + (size_t)b * TLEN;
    int j0 = 4 * c;
    int j3 = (c == 3) ? 14 : j0 + 3;   // clamp OOB tag-15 load (value never used)

    // ---- t = 0 ----
    float em0 = lg[j0], em1 = lg[j0 + 1], em2 = lg[j0 + 2], em3 = lg[j3];
    int ycur = yb[0];
    bool mask = (ycur != PADL);
    float a0 = __expf(em0), a1 = __expf(em1), a2 = __expf(em2);
    float a3 = (c == 3) ? 0.0f : __expf(em3);   // pad tag slot stays exactly 0
    int E = 0;                                   // exact power-of-2 renorm exponent
    float em_acc = 0.0f, tr_acc = 0.0f;
    em_acc += (mask && ycur == j0    ) ? em0 : 0.0f;
    em_acc += (mask && ycur == j0 + 1) ? em1 : 0.0f;
    em_acc += (mask && ycur == j0 + 2) ? em2 : 0.0f;
    em_acc += (mask && ycur == j0 + 3) ? em3 : 0.0f;

    // prefetch t=1
    const float* p1 = lg + NC;
    float n0 = p1[j0], n1 = p1[j0 + 1], n2 = p1[j0 + 2], n3 = p1[j3];
    int ynext = yb[1];

    int yprev; bool pmask;

    for (int t = 1; t < TLEN; t++) {
        em0 = n0; em1 = n1; em2 = n2; em3 = n3;
        yprev = ycur; pmask = mask;
        ycur = ynext;

        // prefetch t+1 (clamped; duplicate last row is harmless)
        int tn = (t + 1 < TLEN) ? (t + 1) : (TLEN - 1);
        const float* pn = lg + (size_t)tn * NC;
        n0 = pn[j0]; n1 = pn[j0 + 1]; n2 = pn[j0 + 2]; n3 = pn[j3];
        ynext = yb[tn];

        mask = (ycur != PADL);

        // s_k = sum_i a_i * expT[i][4c+k]   (linear-space forward matvec)
        float s0a = 0, s0b = 0, s1a = 0, s1b = 0;
        float s2a = 0, s2b = 0, s3a = 0, s3b = 0;
        STEP_I(0,  a0); STEP_I(1,  a1); STEP_I(2,  a2); STEP_I(3,  a3);
        STEP_I(4,  a0); STEP_I(5,  a1); STEP_I(6,  a2); STEP_I(7,  a3);
        STEP_I(8,  a0); STEP_I(9,  a1); STEP_I(10, a2); STEP_I(11, a3);
        STEP_I(12, a0); STEP_I(13, a1); STEP_I(14, a2);

        float w0 = __expf(em0) * (s0a + s0b);
        float w1 = __expf(em1) * (s1a + s1b);
        float w2 = __expf(em2) * (s2a + s2b);
        float w3 = __expf(em3) * (s3a + s3b);   // c==3: s3==0 -> stays 0

        // masked update (branch-free selects; masked step keeps old alpha)
        a0 = mask ? w0 : a0;
        a1 = mask ? w1 : a1;
        a2 = mask ? w2 : a2;
        a3 = mask ? w3 : a3;

        // gold-path emission pick (only owning lane matches; pad excluded by mask)
        em_acc += (mask && ycur == j0    ) ? em0 : 0.0f;
        em_acc += (mask && ycur == j0 + 1) ? em1 : 0.0f;
        em_acc += (mask && ycur == j0 + 2) ? em2 : 0.0f;
        em_acc += (mask && ycur == j0 + 3) ? em3 : 0.0f;
        // gold-path transition (one lane per group accumulates)
        float tv = sT[yprev * 15 + ycur];       // index <= 240 < 256, padded zeros
        tr_acc += (mask && pmask && c == 0) ? tv : 0.0f;

        // exact power-of-two renormalization every 8 steps (branch is warp-uniform)
        if ((t & 7) == 0) {
            float m = fmaxf(fmaxf(a0, a1), fmaxf(a2, a3));
            m = fmaxf(m, __shfl_xor_sync(0xffffffffu, m, 1, 4));
            m = fmaxf(m, __shfl_xor_sync(0xffffffffu, m, 2, 4));
            int ex = ((__float_as_int(m) >> 23) & 0xff) - 127;
            float sc = __int_as_float((127 - ex) << 23);   // exact 2^-ex
            a0 *= sc; a1 *= sc; a2 *= sc; a3 *= sc;
            E += ex;
        }
    }

    // logZ = E*ln2 + log(sum_j a_j)
    float sA = (a0 + a1) + (a2 + a3);
    sA += __shfl_xor_sync(0xffffffffu, sA, 1, 4);
    sA += __shfl_xor_sync(0xffffffffu, sA, 2, 4);
    float path = em_acc + tr_acc;
    path += __shfl_xor_sync(0xffffffffu, path, 1, 4);
    path += __shfl_xor_sync(0xffffffffu, path, 2, 4);

    float logZ = (float)E * 0.6931471805599453f + logf(sA);
    float nll = logZ - path;
    nll = fminf(fmaxf(nll, 0.0f), 1000000.0f);

    // nll is identical across the 4 lanes of a group; xor-4/8/16 sums one copy
    // per group (lanes mixed by these xors share lane&3), so lane 0 holds the
    // exact 8-sequence sum — NO dedup factor.
    float w = nll;
    w += __shfl_xor_sync(0xffffffffu, w, 4);
    w += __shfl_xor_sync(0xffffffffu, w, 8);
    w += __shfl_xor_sync(0xffffffffu, w, 16);
    if (lane == 0) g_partials[warpId] = w;
}

__global__ void crf_reduce(float* out) {
    __shared__ double s[NWARPS];
    int t = threadIdx.x;
    s[t] = (double)g_partials[t];
    __syncthreads();
    for (int o = NWARPS / 2; o > 0; o >>= 1) {
        if (t < o) s[t] += s[t + o];
        __syncthreads();
    }
    if (t == 0) out[0] = (float)(s[0] / (double)NSEQ);
}

extern "C" void kernel_launch(void* const* d_in, const int* in_sizes, int n_in,
                              void* d_out, int out_size) {
    const float* logits = (const float*)d_in[0];
    const int*   yt     = (const int*)d_in[1];
    const float* trans  = (const float*)d_in[2];
    crf_fwd<<<256, 64>>>(logits, yt, trans);
    crf_reduce<<<1, NWARPS>>>((float*)d_out);
}